// round 1
// baseline (speedup 1.0000x reference)
#include <cuda_runtime.h>
#include <cstdint>
#include <cstddef>

#define N_NODES 16384
#define E_EDGES 262144
#define F_IN    1024
#define H1_DIM  256
#define NZ_DIM  64

// ---------------- scratch (static device globals; no runtime allocation) ----
__device__ float g_support1[N_NODES * H1_DIM];   // x@W1          (16 MB)
__device__ float g_hidden1 [N_NODES * H1_DIM];   // relu(spmm1)   (16 MB)
__device__ float g_support2[N_NODES * NZ_DIM];   // hidden1@W2    ( 4 MB)
__device__ int   g_off   [N_NODES + 1];
__device__ int   g_cursor[N_NODES];
__device__ int   g_eidx  [E_EDGES];

// ---------------- CSR build ------------------------------------------------
__global__ void k_zero_counts() {
    int i = blockIdx.x * blockDim.x + threadIdx.x;
    if (i < N_NODES) g_cursor[i] = 0;
}

__global__ void k_hist(const int* __restrict__ ei) {
    int e = blockIdx.x * blockDim.x + threadIdx.x;
    if (e < E_EDGES) atomicAdd(&g_cursor[ei[E_EDGES + e]], 1);
}

// single block, 256 threads, 64 counts per thread
__global__ void k_scan() {
    __shared__ int part[256];
    const int t = threadIdx.x;
    const int base = t * (N_NODES / 256);
    int s = 0;
#pragma unroll
    for (int j = 0; j < N_NODES / 256; j++) s += g_cursor[base + j];
    part[t] = s;
    __syncthreads();
    for (int off = 1; off < 256; off <<= 1) {
        int v = (t >= off) ? part[t - off] : 0;
        __syncthreads();
        part[t] += v;
        __syncthreads();
    }
    int run = part[t] - s;  // exclusive prefix
#pragma unroll
    for (int j = 0; j < N_NODES / 256; j++) {
        int idx = base + j;
        int c = g_cursor[idx];
        g_off[idx] = run;
        g_cursor[idx] = run;   // reset cursor to bucket start
        run += c;
    }
    if (t == 255) g_off[N_NODES] = run;
}

__global__ void k_scatter(const int* __restrict__ ei) {
    int e = blockIdx.x * blockDim.x + threadIdx.x;
    if (e < E_EDGES) {
        int d = ei[E_EDGES + e];
        int p = atomicAdd(&g_cursor[d], 1);
        g_eidx[p] = e;
    }
}

// ---------------- SpMM (gather by dst) + ReLU ------------------------------
// one block = one dst row, 256 lanes cover d=256
__global__ void k_spmm_relu_256(const float* __restrict__ in,
                                const float* __restrict__ ew,
                                const int*   __restrict__ ei,
                                float* __restrict__ out) {
    const int row = blockIdx.x;
    const int t   = threadIdx.x;
    const int beg = g_off[row], end = g_off[row + 1];
    float acc = 0.f;
    for (int p = beg; p < end; p++) {
        int e   = g_eidx[p];
        float w = __ldg(&ew[e]);
        int s   = __ldg(&ei[e]);
        acc += w * __ldg(&in[(size_t)s * H1_DIM + t]);
    }
    out[(size_t)row * H1_DIM + t] = fmaxf(acc, 0.f);
}

// 4 dst rows per block, 64 lanes each (d=64)
__global__ void k_spmm_relu_64(const float* __restrict__ in,
                               const float* __restrict__ ew,
                               const int*   __restrict__ ei,
                               float* __restrict__ out) {
    const int t    = threadIdx.x;
    const int sub  = t >> 6;
    const int lane = t & 63;
    const int row  = blockIdx.x * 4 + sub;
    const int beg = g_off[row], end = g_off[row + 1];
    float acc = 0.f;
    for (int p = beg; p < end; p++) {
        int e   = g_eidx[p];
        float w = __ldg(&ew[e]);
        int s   = __ldg(&ei[e]);
        acc += w * __ldg(&in[(size_t)s * NZ_DIM + lane]);
    }
    out[(size_t)row * NZ_DIM + lane] = fmaxf(acc, 0.f);
}

// ---------------- TF32 tensor-core GEMM ------------------------------------
__device__ __forceinline__ float f2tf32(float x) {
    uint32_t u;
    asm("cvt.rna.tf32.f32 %0, %1;" : "=r"(u) : "f"(x));
    return __uint_as_float(u);
}

__device__ __forceinline__ void mma_tf32(float (&d)[4], const uint32_t (&a)[4],
                                         const uint32_t (&b)[2]) {
    asm volatile(
        "mma.sync.aligned.m16n8k8.row.col.f32.tf32.tf32.f32 "
        "{%0,%1,%2,%3}, {%4,%5,%6,%7}, {%8,%9}, {%0,%1,%2,%3};"
        : "+f"(d[0]), "+f"(d[1]), "+f"(d[2]), "+f"(d[3])
        : "r"(a[0]), "r"(a[1]), "r"(a[2]), "r"(a[3]), "r"(b[0]), "r"(b[1]));
}

// C[M x Nc] = A[M x K](row-major) * op(B)
// BT=true : B stored [Nc x K] row-major (i.e. compute A * B^T — used for z@z.T)
// BT=false: B stored [K x Nc] row-major (normal GEMM)
template <int BM, int BN, int BK, bool BT>
__global__ void __launch_bounds__(256, 1)
k_gemm(const float* __restrict__ A, const float* __restrict__ B,
       float* __restrict__ C, int M, int Nc, int K) {
    constexpr int WM = BM / 2;      // 2 warps along M
    constexpr int WN = BN / 4;      // 4 warps along N
    constexpr int MI = WM / 16;
    constexpr int NI = WN / 8;
    __shared__ float As[BM][BK + 4];
    __shared__ float Bs[BN][BK + 4];

    const int tid  = threadIdx.x;
    const int warp = tid >> 5, lane = tid & 31;
    const int wm = warp & 1, wn = warp >> 1;
    const int bm0 = blockIdx.y * BM, bn0 = blockIdx.x * BN;
    const int g = lane >> 2, c = lane & 3;

    float acc[MI][NI][4];
#pragma unroll
    for (int mi = 0; mi < MI; mi++)
#pragma unroll
        for (int ni = 0; ni < NI; ni++)
#pragma unroll
            for (int j = 0; j < 4; j++) acc[mi][ni][j] = 0.f;

    for (int kt = 0; kt < K; kt += BK) {
        // --- load A tile (row-major, coalesced float4) ---
#pragma unroll
        for (int i = 0; i < BM * BK / 4 / 256; i++) {
            int v = tid + i * 256;
            int r = v / (BK / 4), cv = v % (BK / 4);
            float4 q = *reinterpret_cast<const float4*>(
                &A[(size_t)(bm0 + r) * K + kt + cv * 4]);
            As[r][cv * 4 + 0] = f2tf32(q.x);
            As[r][cv * 4 + 1] = f2tf32(q.y);
            As[r][cv * 4 + 2] = f2tf32(q.z);
            As[r][cv * 4 + 3] = f2tf32(q.w);
        }
        // --- load B tile ---
        if (BT) {
#pragma unroll
            for (int i = 0; i < BN * BK / 4 / 256; i++) {
                int v = tid + i * 256;
                int r = v / (BK / 4), cv = v % (BK / 4);
                float4 q = *reinterpret_cast<const float4*>(
                    &B[(size_t)(bn0 + r) * K + kt + cv * 4]);
                Bs[r][cv * 4 + 0] = f2tf32(q.x);
                Bs[r][cv * 4 + 1] = f2tf32(q.y);
                Bs[r][cv * 4 + 2] = f2tf32(q.z);
                Bs[r][cv * 4 + 3] = f2tf32(q.w);
            }
        } else {
#pragma unroll
            for (int i = 0; i < BK * BN / 4 / 256; i++) {
                int v = tid + i * 256;
                int kk = v / (BN / 4), nv = v % (BN / 4);
                float4 q = *reinterpret_cast<const float4*>(
                    &B[(size_t)(kt + kk) * Nc + bn0 + nv * 4]);
                Bs[nv * 4 + 0][kk] = f2tf32(q.x);
                Bs[nv * 4 + 1][kk] = f2tf32(q.y);
                Bs[nv * 4 + 2][kk] = f2tf32(q.z);
                Bs[nv * 4 + 3][kk] = f2tf32(q.w);
            }
        }
        __syncthreads();

#pragma unroll
        for (int ks = 0; ks < BK / 8; ks++) {
            const int k0 = ks * 8;
            uint32_t af[MI][4];
            uint32_t bf[NI][2];
#pragma unroll
            for (int mi = 0; mi < MI; mi++) {
                int r = wm * WM + mi * 16 + g;
                af[mi][0] = __float_as_uint(As[r][k0 + c]);
                af[mi][1] = __float_as_uint(As[r + 8][k0 + c]);
                af[mi][2] = __float_as_uint(As[r][k0 + 4 + c]);
                af[mi][3] = __float_as_uint(As[r + 8][k0 + 4 + c]);
            }
#pragma unroll
            for (int ni = 0; ni < NI; ni++) {
                int n = wn * WN + ni * 8 + g;
                bf[ni][0] = __float_as_uint(Bs[n][k0 + c]);
                bf[ni][1] = __float_as_uint(Bs[n][k0 + 4 + c]);
            }
#pragma unroll
            for (int mi = 0; mi < MI; mi++)
#pragma unroll
                for (int ni = 0; ni < NI; ni++)
                    mma_tf32(acc[mi][ni], af[mi], bf[ni]);
        }
        __syncthreads();
    }

    // --- epilogue: float2 stores ---
#pragma unroll
    for (int mi = 0; mi < MI; mi++)
#pragma unroll
        for (int ni = 0; ni < NI; ni++) {
            int r  = bm0 + wm * WM + mi * 16 + g;
            int cc = bn0 + wn * WN + ni * 8 + c * 2;
            *reinterpret_cast<float2*>(&C[(size_t)r * Nc + cc]) =
                make_float2(acc[mi][ni][0], acc[mi][ni][1]);
            *reinterpret_cast<float2*>(&C[(size_t)(r + 8) * Nc + cc]) =
                make_float2(acc[mi][ni][2], acc[mi][ni][3]);
        }
}

// ---------------- launch ----------------------------------------------------
extern "C" void kernel_launch(void* const* d_in, const int* in_sizes, int n_in,
                              void* d_out, int out_size) {
    const float* x  = (const float*)d_in[0];
    const float* W1 = (const float*)d_in[1];
    const float* W2 = (const float*)d_in[2];
    const float* ew = (const float*)d_in[3];
    const int*   ei = (const int*)d_in[4];

    float* out  = (float*)d_out;
    float* abar = out;                                   // [N, N]
    float* z    = out + (size_t)N_NODES * N_NODES;       // [N, NZ]

    float *s1, *h1, *s2;
    cudaGetSymbolAddress((void**)&s1, g_support1);
    cudaGetSymbolAddress((void**)&h1, g_hidden1);
    cudaGetSymbolAddress((void**)&s2, g_support2);

    // CSR-by-dst build (per-launch, deterministic counts)
    k_zero_counts<<<N_NODES / 256, 256>>>();
    k_hist<<<E_EDGES / 256, 256>>>(ei);
    k_scan<<<1, 256>>>();
    k_scatter<<<E_EDGES / 256, 256>>>(ei);

    // support1 = x @ W1   [16384,1024]x[1024,256]
    k_gemm<128, 128, 32, false><<<dim3(H1_DIM / 128, N_NODES / 128), 256>>>(
        x, W1, s1, N_NODES, H1_DIM, F_IN);

    // hidden1 = relu(spmm(support1))
    k_spmm_relu_256<<<N_NODES, 256>>>(s1, ew, ei, h1);

    // support2 = hidden1 @ W2   [16384,256]x[256,64]
    k_gemm<128, 64, 32, false><<<dim3(1, N_NODES / 128), 256>>>(
        h1, W2, s2, N_NODES, NZ_DIM, H1_DIM);

    // z = relu(spmm(support2))
    k_spmm_relu_64<<<N_NODES / 4, 256>>>(s2, ew, ei, z);

    // a_bar = z @ z^T   [16384,64] x [64,16384]
    k_gemm<128, 128, 32, true><<<dim3(N_NODES / 128, N_NODES / 128), 256>>>(
        z, z, abar, N_NODES, N_NODES, NZ_DIM);
}

// round 2
// speedup vs baseline: 1.4901x; 1.4901x over previous
#include <cuda_runtime.h>
#include <cstdint>
#include <cstddef>

#define N_NODES 16384
#define E_EDGES 262144
#define F_IN    1024
#define H1_DIM  256
#define NZ_DIM  64

// ---------------- scratch ----------------------------------------------------
__device__ float g_support1[N_NODES * H1_DIM];
__device__ float g_hidden1 [N_NODES * H1_DIM];
__device__ float g_support2[N_NODES * NZ_DIM];
__device__ int   g_off   [N_NODES + 1];
__device__ int   g_cursor[N_NODES];
__device__ int2  g_srcw  [E_EDGES];   // packed (src, weight-bits) per CSR slot

// ---------------- small helpers ----------------------------------------------
__device__ __forceinline__ uint32_t f2tf32(float x) {
    uint32_t u;
    asm("cvt.rna.tf32.f32 %0, %1;" : "=r"(u) : "f"(x));
    return u;
}
__device__ __forceinline__ void cp16(uint32_t s, const void* g) {
    asm volatile("cp.async.cg.shared.global [%0], [%1], 16;\n" ::"r"(s), "l"(g));
}
__device__ __forceinline__ void cp_commit() {
    asm volatile("cp.async.commit_group;\n");
}
template <int N>
__device__ __forceinline__ void cp_wait() {
    asm volatile("cp.async.wait_group %0;\n" ::"n"(N));
}

__device__ __forceinline__ void mma_tf32(float (&d)[4], const uint32_t (&a)[4],
                                         const uint32_t (&b)[2]) {
    asm volatile(
        "mma.sync.aligned.m16n8k8.row.col.f32.tf32.tf32.f32 "
        "{%0,%1,%2,%3}, {%4,%5,%6,%7}, {%8,%9}, {%0,%1,%2,%3};"
        : "+f"(d[0]), "+f"(d[1]), "+f"(d[2]), "+f"(d[3])
        : "r"(a[0]), "r"(a[1]), "r"(a[2]), "r"(a[3]), "r"(b[0]), "r"(b[1]));
}

// ---------------- CSR build ---------------------------------------------------
__global__ void k_zero_counts() {
    int i = blockIdx.x * blockDim.x + threadIdx.x;
    if (i < N_NODES) g_cursor[i] = 0;
}
__global__ void k_hist(const int* __restrict__ ei) {
    int e = blockIdx.x * blockDim.x + threadIdx.x;
    if (e < E_EDGES) atomicAdd(&g_cursor[ei[E_EDGES + e]], 1);
}
__global__ void k_scan() {
    __shared__ int part[256];
    const int t = threadIdx.x;
    const int base = t * (N_NODES / 256);
    int s = 0;
#pragma unroll
    for (int j = 0; j < N_NODES / 256; j++) s += g_cursor[base + j];
    part[t] = s;
    __syncthreads();
    for (int off = 1; off < 256; off <<= 1) {
        int v = (t >= off) ? part[t - off] : 0;
        __syncthreads();
        part[t] += v;
        __syncthreads();
    }
    int run = part[t] - s;
#pragma unroll
    for (int j = 0; j < N_NODES / 256; j++) {
        int idx = base + j;
        int c = g_cursor[idx];
        g_off[idx] = run;
        g_cursor[idx] = run;
        run += c;
    }
    if (t == 255) g_off[N_NODES] = run;
}
__global__ void k_scatter(const int* __restrict__ ei, const float* __restrict__ ew) {
    int e = blockIdx.x * blockDim.x + threadIdx.x;
    if (e < E_EDGES) {
        int d = ei[E_EDGES + e];
        int p = atomicAdd(&g_cursor[d], 1);
        g_srcw[p] = make_int2(ei[e], __float_as_int(ew[e]));
    }
}

// ---------------- SpMM + ReLU -------------------------------------------------
__global__ void k_spmm_relu_256(const float* __restrict__ in,
                                float* __restrict__ out) {
    const int row = blockIdx.x;
    const int t   = threadIdx.x;
    const int beg = g_off[row], end = g_off[row + 1];
    float acc = 0.f;
    int p = beg;
    for (; p + 2 <= end; p += 2) {
        int2 v0 = g_srcw[p];
        int2 v1 = g_srcw[p + 1];
        float r0 = __ldg(&in[(size_t)v0.x * H1_DIM + t]);
        float r1 = __ldg(&in[(size_t)v1.x * H1_DIM + t]);
        acc += __int_as_float(v0.y) * r0;
        acc += __int_as_float(v1.y) * r1;
    }
    if (p < end) {
        int2 v = g_srcw[p];
        acc += __int_as_float(v.y) * __ldg(&in[(size_t)v.x * H1_DIM + t]);
    }
    out[(size_t)row * H1_DIM + t] = fmaxf(acc, 0.f);
}

__global__ void k_spmm_relu_64(const float* __restrict__ in,
                               float* __restrict__ out) {
    const int t    = threadIdx.x;
    const int sub  = t >> 6;
    const int lane = t & 63;
    const int row  = blockIdx.x * 4 + sub;
    const int beg = g_off[row], end = g_off[row + 1];
    float acc = 0.f;
    int p = beg;
    for (; p + 2 <= end; p += 2) {
        int2 v0 = g_srcw[p];
        int2 v1 = g_srcw[p + 1];
        float r0 = __ldg(&in[(size_t)v0.x * NZ_DIM + lane]);
        float r1 = __ldg(&in[(size_t)v1.x * NZ_DIM + lane]);
        acc += __int_as_float(v0.y) * r0;
        acc += __int_as_float(v1.y) * r1;
    }
    if (p < end) {
        int2 v = g_srcw[p];
        acc += __int_as_float(v.y) * __ldg(&in[(size_t)v.x * NZ_DIM + lane]);
    }
    out[(size_t)row * NZ_DIM + lane] = fmaxf(acc, 0.f);
}

// ---------------- pipelined TF32 GEMM (B row-major [K,Nc]) --------------------
// 2-stage cp.async double buffering. A in smem m-major pitch BK+4 (conflict-free),
// B in smem k-major pitch BN+8 (conflict-free). cvt.rna at operand fetch.
template <int BM, int BN, int BK>
__global__ void __launch_bounds__(256, 1)
k_gemm(const float* __restrict__ A, const float* __restrict__ B,
       float* __restrict__ C, int M, int Nc, int K) {
    constexpr int WM = BM / 2, WN = BN / 4;
    constexpr int MI = WM / 16, NI = WN / 8;
    constexpr int AP = BK + 4;          // A pitch (floats)
    constexpr int BP = BN + 8;          // B pitch (floats)
    constexpr int ASZ = BM * AP;
    constexpr int BSZ = BK * BP;
    constexpr int ACH = BM * BK / (4 * 256);
    constexpr int BCH = BK * BN / (4 * 256);

    extern __shared__ float sm[];
    float* sA0 = sm;                 // [A0][A1][B0][B1]
    float* sB0 = sm + 2 * ASZ;
    const uint32_t smem_u32 = (uint32_t)__cvta_generic_to_shared(sm);

    const int tid  = threadIdx.x;
    const int warp = tid >> 5, lane = tid & 31;
    const int wm = warp & 1, wn = warp >> 1;
    const int bm0 = blockIdx.y * BM, bn0 = blockIdx.x * BN;
    const int g = lane >> 2, c = lane & 3;

    float acc[MI][NI][4];
#pragma unroll
    for (int mi = 0; mi < MI; mi++)
#pragma unroll
        for (int ni = 0; ni < NI; ni++)
#pragma unroll
            for (int j = 0; j < 4; j++) acc[mi][ni][j] = 0.f;

    const int NT = K / BK;

    auto load_tiles = [&](int kt, int st) {
        const float* Ag = A + (size_t)bm0 * K + kt * BK;
        uint32_t abase = smem_u32 + (uint32_t)(st * ASZ) * 4u;
#pragma unroll
        for (int i = 0; i < ACH; i++) {
            int v = tid + i * 256;
            int r = v / (BK / 4), col = (v % (BK / 4)) * 4;
            cp16(abase + (uint32_t)(r * AP + col) * 4u,
                 Ag + (size_t)r * K + col);
        }
        const float* Bg = B + (size_t)(kt * BK) * Nc + bn0;
        uint32_t bbase = smem_u32 + (uint32_t)(2 * ASZ + st * BSZ) * 4u;
#pragma unroll
        for (int i = 0; i < BCH; i++) {
            int v = tid + i * 256;
            int r = v / (BN / 4), col = (v % (BN / 4)) * 4;
            cp16(bbase + (uint32_t)(r * BP + col) * 4u,
                 Bg + (size_t)r * Nc + col);
        }
    };

    load_tiles(0, 0);
    cp_commit();

    for (int kt = 0; kt < NT; kt++) {
        if (kt + 1 < NT) {
            load_tiles(kt + 1, (kt + 1) & 1);
            cp_commit();
            cp_wait<1>();
        } else {
            cp_wait<0>();
        }
        __syncthreads();

        const float* sA = sA0 + (kt & 1) * ASZ;
        const float* sB = sB0 + (kt & 1) * BSZ;
#pragma unroll
        for (int ks = 0; ks < BK / 8; ks++) {
            const int k0 = ks * 8;
            uint32_t af[MI][4];
            uint32_t bf[NI][2];
#pragma unroll
            for (int mi = 0; mi < MI; mi++) {
                int r = wm * WM + mi * 16 + g;
                af[mi][0] = f2tf32(sA[r * AP + k0 + c]);
                af[mi][1] = f2tf32(sA[(r + 8) * AP + k0 + c]);
                af[mi][2] = f2tf32(sA[r * AP + k0 + 4 + c]);
                af[mi][3] = f2tf32(sA[(r + 8) * AP + k0 + 4 + c]);
            }
#pragma unroll
            for (int ni = 0; ni < NI; ni++) {
                int n = wn * WN + ni * 8 + g;
                bf[ni][0] = f2tf32(sB[(k0 + c) * BP + n]);
                bf[ni][1] = f2tf32(sB[(k0 + 4 + c) * BP + n]);
            }
#pragma unroll
            for (int mi = 0; mi < MI; mi++)
#pragma unroll
                for (int ni = 0; ni < NI; ni++)
                    mma_tf32(acc[mi][ni], af[mi], bf[ni]);
        }
        __syncthreads();
    }

#pragma unroll
    for (int mi = 0; mi < MI; mi++)
#pragma unroll
        for (int ni = 0; ni < NI; ni++) {
            int r  = bm0 + wm * WM + mi * 16 + g;
            int cc = bn0 + wn * WN + ni * 8 + c * 2;
            *reinterpret_cast<float2*>(&C[(size_t)r * Nc + cc]) =
                make_float2(acc[mi][ni][0], acc[mi][ni][1]);
            *reinterpret_cast<float2*>(&C[(size_t)(r + 8) * Nc + cc]) =
                make_float2(acc[mi][ni][2], acc[mi][ni][3]);
        }
}

// ---------------- specialized z @ z^T (K=64, single pass) --------------------
__global__ void __launch_bounds__(256, 1)
k_zzt(const float* __restrict__ Z, float* __restrict__ C) {
    constexpr int P = 68;   // pitch: 4g+c bank-conflict-free, 16B multiple
    extern __shared__ float sm[];
    float* sA = sm;
    float* sB = sm + 128 * P;
    const uint32_t smem_u32 = (uint32_t)__cvta_generic_to_shared(sm);

    const int tid  = threadIdx.x;
    const int warp = tid >> 5, lane = tid & 31;
    const int wm = warp & 1, wn = warp >> 1;
    const int bm0 = blockIdx.y * 128, bn0 = blockIdx.x * 128;
    const int g = lane >> 2, c = lane & 3;

    // load both 128x64 tiles of z (row-major, 16 chunks of 16B per row)
#pragma unroll
    for (int i = 0; i < 8; i++) {
        int v = tid + i * 256;
        int r = v / 16, col = (v % 16) * 4;
        cp16(smem_u32 + (uint32_t)(r * P + col) * 4u,
             Z + (size_t)(bm0 + r) * NZ_DIM + col);
    }
#pragma unroll
    for (int i = 0; i < 8; i++) {
        int v = tid + i * 256;
        int r = v / 16, col = (v % 16) * 4;
        cp16(smem_u32 + (uint32_t)(128 * P + r * P + col) * 4u,
             Z + (size_t)(bn0 + r) * NZ_DIM + col);
    }
    cp_commit();
    cp_wait<0>();
    __syncthreads();

    float acc[4][4][4];
#pragma unroll
    for (int mi = 0; mi < 4; mi++)
#pragma unroll
        for (int ni = 0; ni < 4; ni++)
#pragma unroll
            for (int j = 0; j < 4; j++) acc[mi][ni][j] = 0.f;

#pragma unroll
    for (int ks = 0; ks < 8; ks++) {
        const int k0 = ks * 8;
        uint32_t af[4][4];
        uint32_t bf[4][2];
#pragma unroll
        for (int mi = 0; mi < 4; mi++) {
            int r = wm * 64 + mi * 16 + g;
            af[mi][0] = f2tf32(sA[r * P + k0 + c]);
            af[mi][1] = f2tf32(sA[(r + 8) * P + k0 + c]);
            af[mi][2] = f2tf32(sA[r * P + k0 + 4 + c]);
            af[mi][3] = f2tf32(sA[(r + 8) * P + k0 + 4 + c]);
        }
#pragma unroll
        for (int ni = 0; ni < 4; ni++) {
            int n = wn * 32 + ni * 8 + g;
            bf[ni][0] = f2tf32(sB[n * P + k0 + c]);
            bf[ni][1] = f2tf32(sB[n * P + k0 + 4 + c]);
        }
#pragma unroll
        for (int mi = 0; mi < 4; mi++)
#pragma unroll
            for (int ni = 0; ni < 4; ni++)
                mma_tf32(acc[mi][ni], af[mi], bf[ni]);
    }

#pragma unroll
    for (int mi = 0; mi < 4; mi++)
#pragma unroll
        for (int ni = 0; ni < 4; ni++) {
            int r  = bm0 + wm * 64 + mi * 16 + g;
            int cc = bn0 + wn * 32 + ni * 8 + c * 2;
            *reinterpret_cast<float2*>(&C[(size_t)r * N_NODES + cc]) =
                make_float2(acc[mi][ni][0], acc[mi][ni][1]);
            *reinterpret_cast<float2*>(&C[(size_t)(r + 8) * N_NODES + cc]) =
                make_float2(acc[mi][ni][2], acc[mi][ni][3]);
        }
}

// ---------------- launch ------------------------------------------------------
extern "C" void kernel_launch(void* const* d_in, const int* in_sizes, int n_in,
                              void* d_out, int out_size) {
    const float* x  = (const float*)d_in[0];
    const float* W1 = (const float*)d_in[1];
    const float* W2 = (const float*)d_in[2];
    const float* ew = (const float*)d_in[3];
    const int*   ei = (const int*)d_in[4];

    float* out  = (float*)d_out;
    float* abar = out;
    float* z    = out + (size_t)N_NODES * N_NODES;

    float *s1, *h1, *s2;
    cudaGetSymbolAddress((void**)&s1, g_support1);
    cudaGetSymbolAddress((void**)&h1, g_hidden1);
    cudaGetSymbolAddress((void**)&s2, g_support2);

    // dynamic smem sizes
    constexpr int SM_G1  = 2 * (128 * 36 + 32 * 136) * 4;  // 71680
    constexpr int SM_G2  = 2 * (128 * 36 + 32 * 72) * 4;   // 55296
    constexpr int SM_ZZT = 2 * 128 * 68 * 4;               // 69632

    cudaFuncSetAttribute(k_gemm<128, 128, 32>,
                         cudaFuncAttributeMaxDynamicSharedMemorySize, SM_G1);
    cudaFuncSetAttribute(k_gemm<128, 64, 32>,
                         cudaFuncAttributeMaxDynamicSharedMemorySize, SM_G2);
    cudaFuncSetAttribute(k_zzt,
                         cudaFuncAttributeMaxDynamicSharedMemorySize, SM_ZZT);

    // CSR-by-dst
    k_zero_counts<<<N_NODES / 256, 256>>>();
    k_hist<<<E_EDGES / 256, 256>>>(ei);
    k_scan<<<1, 256>>>();
    k_scatter<<<E_EDGES / 256, 256>>>(ei, ew);

    // support1 = x @ W1
    k_gemm<128, 128, 32><<<dim3(H1_DIM / 128, N_NODES / 128), 256, SM_G1>>>(
        x, W1, s1, N_NODES, H1_DIM, F_IN);

    // hidden1 = relu(spmm(support1))
    k_spmm_relu_256<<<N_NODES, 256>>>(s1, h1);

    // support2 = hidden1 @ W2
    k_gemm<128, 64, 32><<<dim3(1, N_NODES / 128), 256, SM_G2>>>(
        h1, W2, s2, N_NODES, NZ_DIM, H1_DIM);

    // z = relu(spmm(support2))
    k_spmm_relu_64<<<N_NODES / 4, 256>>>(s2, z);

    // a_bar = z @ z^T
    k_zzt<<<dim3(N_NODES / 128, N_NODES / 128), 256, SM_ZZT>>>(z, abar);
}

// round 3
// speedup vs baseline: 1.7538x; 1.1770x over previous
#include <cuda_runtime.h>
#include <cstdint>
#include <cstddef>

#define N_NODES 16384
#define E_EDGES 262144
#define F_IN    1024
#define H1_DIM  256
#define NZ_DIM  64

// ---------------- scratch ----------------------------------------------------
__device__ float g_support1[N_NODES * H1_DIM];
__device__ float g_hidden1 [N_NODES * H1_DIM];
__device__ float g_support2[N_NODES * NZ_DIM];
__device__ int   g_off   [N_NODES + 1];
__device__ int   g_cursor[N_NODES];
__device__ int2  g_srcw  [E_EDGES];

// ---------------- helpers -----------------------------------------------------
__device__ __forceinline__ uint32_t f2tf32(float x) {
    uint32_t u;
    asm("cvt.rna.tf32.f32 %0, %1;" : "=r"(u) : "f"(x));
    return u;
}
__device__ __forceinline__ void cp16(uint32_t s, const void* g) {
    asm volatile("cp.async.cg.shared.global [%0], [%1], 16;\n" ::"r"(s), "l"(g));
}
__device__ __forceinline__ void cp_commit() {
    asm volatile("cp.async.commit_group;\n");
}
template <int N>
__device__ __forceinline__ void cp_wait() {
    asm volatile("cp.async.wait_group %0;\n" ::"n"(N));
}
__device__ __forceinline__ void mma_tf32(float (&d)[4], const uint32_t (&a)[4],
                                         const uint32_t (&b)[2]) {
    asm volatile(
        "mma.sync.aligned.m16n8k8.row.col.f32.tf32.tf32.f32 "
        "{%0,%1,%2,%3}, {%4,%5,%6,%7}, {%8,%9}, {%0,%1,%2,%3};"
        : "+f"(d[0]), "+f"(d[1]), "+f"(d[2]), "+f"(d[3])
        : "r"(a[0]), "r"(a[1]), "r"(a[2]), "r"(a[3]), "r"(b[0]), "r"(b[1]));
}

// ---------------- CSR build ----------------------------------------------------
__global__ void k_zero_counts() {
    int i = blockIdx.x * blockDim.x + threadIdx.x;
    if (i < N_NODES) g_cursor[i] = 0;
}
__global__ void k_hist(const int* __restrict__ ei) {
    int e = blockIdx.x * blockDim.x + threadIdx.x;
    if (e < E_EDGES) atomicAdd(&g_cursor[ei[E_EDGES + e]], 1);
}
__global__ void k_scan() {
    __shared__ int part[256];
    const int t = threadIdx.x;
    const int base = t * (N_NODES / 256);
    int s = 0;
#pragma unroll
    for (int j = 0; j < N_NODES / 256; j++) s += g_cursor[base + j];
    part[t] = s;
    __syncthreads();
    for (int off = 1; off < 256; off <<= 1) {
        int v = (t >= off) ? part[t - off] : 0;
        __syncthreads();
        part[t] += v;
        __syncthreads();
    }
    int run = part[t] - s;
#pragma unroll
    for (int j = 0; j < N_NODES / 256; j++) {
        int idx = base + j;
        int c = g_cursor[idx];
        g_off[idx] = run;
        g_cursor[idx] = run;
        run += c;
    }
    if (t == 255) g_off[N_NODES] = run;
}
__global__ void k_scatter(const int* __restrict__ ei, const float* __restrict__ ew) {
    int e = blockIdx.x * blockDim.x + threadIdx.x;
    if (e < E_EDGES) {
        int d = ei[E_EDGES + e];
        int p = atomicAdd(&g_cursor[d], 1);
        g_srcw[p] = make_int2(ei[e], __float_as_int(ew[e]));
    }
}

// ---------------- SpMM + ReLU (smem-staged edge lists, full MLP) ---------------
__global__ void __launch_bounds__(256) k_spmm_relu_256(
    const float* __restrict__ in, float* __restrict__ out) {
    __shared__ int2 se[256];
    const int row = blockIdx.x;
    const int t   = threadIdx.x;
    const int beg = g_off[row], end = g_off[row + 1];
    float acc = 0.f;
    for (int cs = beg; cs < end; cs += 256) {
        int m = min(256, end - cs);
        __syncthreads();
        if (t < m) se[t] = g_srcw[cs + t];
        __syncthreads();
        int j = 0;
        for (; j + 4 <= m; j += 4) {
            int2 v0 = se[j], v1 = se[j + 1], v2 = se[j + 2], v3 = se[j + 3];
            float r0 = __ldg(&in[(size_t)v0.x * H1_DIM + t]);
            float r1 = __ldg(&in[(size_t)v1.x * H1_DIM + t]);
            float r2 = __ldg(&in[(size_t)v2.x * H1_DIM + t]);
            float r3 = __ldg(&in[(size_t)v3.x * H1_DIM + t]);
            acc += __int_as_float(v0.y) * r0;
            acc += __int_as_float(v1.y) * r1;
            acc += __int_as_float(v2.y) * r2;
            acc += __int_as_float(v3.y) * r3;
        }
        for (; j < m; j++) {
            int2 v = se[j];
            acc += __int_as_float(v.y) * __ldg(&in[(size_t)v.x * H1_DIM + t]);
        }
    }
    out[(size_t)row * H1_DIM + t] = fmaxf(acc, 0.f);
}

__global__ void __launch_bounds__(256) k_spmm_relu_64(
    const float* __restrict__ in, float* __restrict__ out) {
    __shared__ int2 se[4][64];
    __shared__ int sdeg[4];
    const int t    = threadIdx.x;
    const int sub  = t >> 6;
    const int lane = t & 63;
    const int row  = blockIdx.x * 4 + sub;
    const int beg  = g_off[row];
    if (t < 4) sdeg[t] = g_off[blockIdx.x * 4 + t + 1] - g_off[blockIdx.x * 4 + t];
    __syncthreads();
    const int deg  = sdeg[sub];
    const int nch  = (max(max(sdeg[0], sdeg[1]), max(sdeg[2], sdeg[3])) + 63) >> 6;
    float acc = 0.f;
    for (int ch = 0; ch < nch; ch++) {
        int m = min(64, deg - ch * 64);
        __syncthreads();
        if (lane < m) se[sub][lane] = g_srcw[beg + ch * 64 + lane];
        __syncthreads();
        int j = 0;
        for (; j + 4 <= m; j += 4) {
            int2 v0 = se[sub][j], v1 = se[sub][j + 1];
            int2 v2 = se[sub][j + 2], v3 = se[sub][j + 3];
            float r0 = __ldg(&in[(size_t)v0.x * NZ_DIM + lane]);
            float r1 = __ldg(&in[(size_t)v1.x * NZ_DIM + lane]);
            float r2 = __ldg(&in[(size_t)v2.x * NZ_DIM + lane]);
            float r3 = __ldg(&in[(size_t)v3.x * NZ_DIM + lane]);
            acc += __int_as_float(v0.y) * r0;
            acc += __int_as_float(v1.y) * r1;
            acc += __int_as_float(v2.y) * r2;
            acc += __int_as_float(v3.y) * r3;
        }
        for (; j < m; j++) {
            int2 v = se[sub][j];
            acc += __int_as_float(v.y) * __ldg(&in[(size_t)v.x * NZ_DIM + lane]);
        }
    }
    out[(size_t)row * NZ_DIM + lane] = fmaxf(acc, 0.f);
}

// ---------------- pipelined TF32 GEMM (B row-major [K,Nc]) ---------------------
template <int BM, int BN, int BK>
__global__ void __launch_bounds__(256, 2)
k_gemm(const float* __restrict__ A, const float* __restrict__ B,
       float* __restrict__ C, int M, int Nc, int K) {
    constexpr int WM = BM / 2, WN = BN / 4;
    constexpr int MI = WM / 16, NI = WN / 8;
    constexpr int AP = BK + 4;
    constexpr int BP = BN + 8;
    constexpr int ASZ = BM * AP;
    constexpr int BSZ = BK * BP;
    constexpr int ACH = BM * BK / (4 * 256);
    constexpr int BCH = BK * BN / (4 * 256);

    extern __shared__ float sm[];
    float* sA0 = sm;
    float* sB0 = sm + 2 * ASZ;
    const uint32_t smem_u32 = (uint32_t)__cvta_generic_to_shared(sm);

    const int tid  = threadIdx.x;
    const int warp = tid >> 5, lane = tid & 31;
    const int wm = warp & 1, wn = warp >> 1;
    const int bm0 = blockIdx.y * BM, bn0 = blockIdx.x * BN;
    const int g = lane >> 2, c = lane & 3;

    float acc[MI][NI][4];
#pragma unroll
    for (int mi = 0; mi < MI; mi++)
#pragma unroll
        for (int ni = 0; ni < NI; ni++)
#pragma unroll
            for (int j = 0; j < 4; j++) acc[mi][ni][j] = 0.f;

    const int NT = K / BK;

    auto load_tiles = [&](int kt, int st) {
        const float* Ag = A + (size_t)bm0 * K + kt * BK;
        uint32_t abase = smem_u32 + (uint32_t)(st * ASZ) * 4u;
#pragma unroll
        for (int i = 0; i < ACH; i++) {
            int v = tid + i * 256;
            int r = v / (BK / 4), col = (v % (BK / 4)) * 4;
            cp16(abase + (uint32_t)(r * AP + col) * 4u, Ag + (size_t)r * K + col);
        }
        const float* Bg = B + (size_t)(kt * BK) * Nc + bn0;
        uint32_t bbase = smem_u32 + (uint32_t)(2 * ASZ + st * BSZ) * 4u;
#pragma unroll
        for (int i = 0; i < BCH; i++) {
            int v = tid + i * 256;
            int r = v / (BN / 4), col = (v % (BN / 4)) * 4;
            cp16(bbase + (uint32_t)(r * BP + col) * 4u, Bg + (size_t)r * Nc + col);
        }
    };

    load_tiles(0, 0);
    cp_commit();

    for (int kt = 0; kt < NT; kt++) {
        if (kt + 1 < NT) {
            load_tiles(kt + 1, (kt + 1) & 1);
            cp_commit();
            cp_wait<1>();
        } else {
            cp_wait<0>();
        }
        __syncthreads();

        const float* sA = sA0 + (kt & 1) * ASZ;
        const float* sB = sB0 + (kt & 1) * BSZ;
#pragma unroll
        for (int ks = 0; ks < BK / 8; ks++) {
            const int k0 = ks * 8;
            uint32_t af[MI][4];
            uint32_t bf[NI][2];
#pragma unroll
            for (int mi = 0; mi < MI; mi++) {
                int r = wm * WM + mi * 16 + g;
                af[mi][0] = f2tf32(sA[r * AP + k0 + c]);
                af[mi][1] = f2tf32(sA[(r + 8) * AP + k0 + c]);
                af[mi][2] = f2tf32(sA[r * AP + k0 + 4 + c]);
                af[mi][3] = f2tf32(sA[(r + 8) * AP + k0 + 4 + c]);
            }
#pragma unroll
            for (int ni = 0; ni < NI; ni++) {
                int n = wn * WN + ni * 8 + g;
                bf[ni][0] = f2tf32(sB[(k0 + c) * BP + n]);
                bf[ni][1] = f2tf32(sB[(k0 + 4 + c) * BP + n]);
            }
#pragma unroll
            for (int mi = 0; mi < MI; mi++)
#pragma unroll
                for (int ni = 0; ni < NI; ni++)
                    mma_tf32(acc[mi][ni], af[mi], bf[ni]);
        }
        __syncthreads();
    }

#pragma unroll
    for (int mi = 0; mi < MI; mi++)
#pragma unroll
        for (int ni = 0; ni < NI; ni++) {
            int r  = bm0 + wm * WM + mi * 16 + g;
            int cc = bn0 + wn * WN + ni * 8 + c * 2;
            *reinterpret_cast<float2*>(&C[(size_t)r * Nc + cc]) =
                make_float2(acc[mi][ni][0], acc[mi][ni][1]);
            *reinterpret_cast<float2*>(&C[(size_t)(r + 8) * Nc + cc]) =
                make_float2(acc[mi][ni][2], acc[mi][ni][3]);
        }
}

// ---------------- z @ z^T, symmetric: lower-triangle blocks only --------------
// tile (bi=row-block, bj=col-block) with bj<=bi computed once; off-diagonal
// tiles are also written transposed at (bj,bi) via an smem transpose stage.
__global__ void __launch_bounds__(256, 2)
k_zzt(const float* __restrict__ Z, float* __restrict__ C) {
    constexpr int P  = 68;    // operand pitch
    constexpr int TP = 132;   // transpose pitch (8c+g bank pattern)
    extern __shared__ float sm[];
    float* sA = sm;
    float* sB = sm + 128 * P;
    const uint32_t smem_u32 = (uint32_t)__cvta_generic_to_shared(sm);

    const int tid  = threadIdx.x;
    const int warp = tid >> 5, lane = tid & 31;
    const int wm = warp & 1, wn = warp >> 1;
    const int g = lane >> 2, c = lane & 3;

    // triangular decode: blockIdx.x -> (bi >= bj)
    int t = blockIdx.x;
    int bi = (int)((sqrtf(8.f * (float)t + 1.f) - 1.f) * 0.5f);
    while ((bi + 1) * (bi + 2) / 2 <= t) bi++;
    while (bi * (bi + 1) / 2 > t) bi--;
    int bj = t - bi * (bi + 1) / 2;
    const int bm0 = bi * 128;   // rows of direct tile
    const int bn0 = bj * 128;   // cols of direct tile

    // load A tile (rows bm0..) and B tile (rows bn0..) of z [16384,64]
#pragma unroll
    for (int i = 0; i < 8; i++) {
        int v = tid + i * 256;
        int r = v / 16, col = (v % 16) * 4;
        cp16(smem_u32 + (uint32_t)(r * P + col) * 4u,
             Z + (size_t)(bm0 + r) * NZ_DIM + col);
    }
#pragma unroll
    for (int i = 0; i < 8; i++) {
        int v = tid + i * 256;
        int r = v / 16, col = (v % 16) * 4;
        cp16(smem_u32 + (uint32_t)(128 * P + r * P + col) * 4u,
             Z + (size_t)(bn0 + r) * NZ_DIM + col);
    }
    cp_commit();
    cp_wait<0>();
    __syncthreads();

    float acc[4][4][4];
#pragma unroll
    for (int mi = 0; mi < 4; mi++)
#pragma unroll
        for (int ni = 0; ni < 4; ni++)
#pragma unroll
            for (int j = 0; j < 4; j++) acc[mi][ni][j] = 0.f;

#pragma unroll
    for (int ks = 0; ks < 8; ks++) {
        const int k0 = ks * 8;
        uint32_t af[4][4];
        uint32_t bf[4][2];
#pragma unroll
        for (int mi = 0; mi < 4; mi++) {
            int r = wm * 64 + mi * 16 + g;
            af[mi][0] = f2tf32(sA[r * P + k0 + c]);
            af[mi][1] = f2tf32(sA[(r + 8) * P + k0 + c]);
            af[mi][2] = f2tf32(sA[r * P + k0 + 4 + c]);
            af[mi][3] = f2tf32(sA[(r + 8) * P + k0 + 4 + c]);
        }
#pragma unroll
        for (int ni = 0; ni < 4; ni++) {
            int n = wn * 32 + ni * 8 + g;
            bf[ni][0] = f2tf32(sB[n * P + k0 + c]);
            bf[ni][1] = f2tf32(sB[n * P + k0 + 4 + c]);
        }
#pragma unroll
        for (int mi = 0; mi < 4; mi++)
#pragma unroll
            for (int ni = 0; ni < 4; ni++)
                mma_tf32(acc[mi][ni], af[mi], bf[ni]);
    }

    // direct store of tile (bm0 rows, bn0 cols)
#pragma unroll
    for (int mi = 0; mi < 4; mi++)
#pragma unroll
        for (int ni = 0; ni < 4; ni++) {
            int r  = bm0 + wm * 64 + mi * 16 + g;
            int cc = bn0 + wn * 32 + ni * 8 + c * 2;
            *reinterpret_cast<float2*>(&C[(size_t)r * N_NODES + cc]) =
                make_float2(acc[mi][ni][0], acc[mi][ni][1]);
            *reinterpret_cast<float2*>(&C[(size_t)(r + 8) * N_NODES + cc]) =
                make_float2(acc[mi][ni][2], acc[mi][ni][3]);
        }

    if (bi == bj) return;

    // transpose stage (reuses operand smem) then coalesced store at (bn0,bm0)
    __syncthreads();
#pragma unroll
    for (int mi = 0; mi < 4; mi++)
#pragma unroll
        for (int ni = 0; ni < 4; ni++) {
            int r  = wm * 64 + mi * 16 + g;
            int cc = wn * 32 + ni * 8 + c * 2;
            sm[(size_t)cc * TP + r]           = acc[mi][ni][0];
            sm[(size_t)(cc + 1) * TP + r]     = acc[mi][ni][1];
            sm[(size_t)cc * TP + r + 8]       = acc[mi][ni][2];
            sm[(size_t)(cc + 1) * TP + r + 8] = acc[mi][ni][3];
        }
    __syncthreads();
#pragma unroll
    for (int i = 0; i < 16; i++) {
        int v = tid + i * 256;
        int j = v >> 5, col = (v & 31) * 4;
        float4 q = *reinterpret_cast<const float4*>(&sm[(size_t)j * TP + col]);
        *reinterpret_cast<float4*>(&C[(size_t)(bn0 + j) * N_NODES + bm0 + col]) = q;
    }
}

// ---------------- launch --------------------------------------------------------
extern "C" void kernel_launch(void* const* d_in, const int* in_sizes, int n_in,
                              void* d_out, int out_size) {
    const float* x  = (const float*)d_in[0];
    const float* W1 = (const float*)d_in[1];
    const float* W2 = (const float*)d_in[2];
    const float* ew = (const float*)d_in[3];
    const int*   ei = (const int*)d_in[4];

    float* out  = (float*)d_out;
    float* abar = out;
    float* z    = out + (size_t)N_NODES * N_NODES;

    float *s1, *h1, *s2;
    cudaGetSymbolAddress((void**)&s1, g_support1);
    cudaGetSymbolAddress((void**)&h1, g_hidden1);
    cudaGetSymbolAddress((void**)&s2, g_support2);

    constexpr int SM_G1  = 2 * (128 * 36 + 32 * 136) * 4;  // 71680
    constexpr int SM_G2  = 2 * (128 * 36 + 32 * 72) * 4;   // 55296
    constexpr int SM_ZZT = 2 * 128 * 68 * 4;               // 69632 (>= 128*132*4)

    cudaFuncSetAttribute(k_gemm<128, 128, 32>,
                         cudaFuncAttributeMaxDynamicSharedMemorySize, SM_G1);
    cudaFuncSetAttribute(k_gemm<128, 64, 32>,
                         cudaFuncAttributeMaxDynamicSharedMemorySize, SM_G2);
    cudaFuncSetAttribute(k_zzt,
                         cudaFuncAttributeMaxDynamicSharedMemorySize, SM_ZZT);

    // CSR-by-dst
    k_zero_counts<<<N_NODES / 256, 256>>>();
    k_hist<<<E_EDGES / 256, 256>>>(ei);
    k_scan<<<1, 256>>>();
    k_scatter<<<E_EDGES / 256, 256>>>(ei, ew);

    // support1 = x @ W1
    k_gemm<128, 128, 32><<<dim3(H1_DIM / 128, N_NODES / 128), 256, SM_G1>>>(
        x, W1, s1, N_NODES, H1_DIM, F_IN);

    // hidden1 = relu(spmm(support1))
    k_spmm_relu_256<<<N_NODES, 256>>>(s1, h1);

    // support2 = hidden1 @ W2
    k_gemm<128, 64, 32><<<dim3(1, N_NODES / 128), 256, SM_G2>>>(
        h1, W2, s2, N_NODES, NZ_DIM, H1_DIM);

    // z = relu(spmm(support2))
    k_spmm_relu_64<<<N_NODES / 4, 256>>>(s2, z);

    // a_bar = z @ z^T (triangular grid, each off-diag tile stored twice)
    const int ntile = N_NODES / 128;
    k_zzt<<<ntile * (ntile + 1) / 2, 256, SM_ZZT>>>(z, abar);
}